// round 15
// baseline (speedup 1.0000x reference)
#include <cuda_runtime.h>
#include <cuda_bf16.h>
#include <cstdint>

#define N_NODES 100000
#define E_EDGES 1600000
#define IN_C 128
#define OUT_C 64
#define NEG_SLOPE 0.2f
#define EPS 1e-16f

// -------- scratch (device globals; no runtime allocation allowed) --------
__device__ __align__(16) float g_h[(size_t)N_NODES * OUT_C];  // transformed features
__device__ float    g_ssrc[N_NODES];
__device__ float    g_sdst[N_NODES];
__device__ __align__(16) int g_src[E_EDGES];
__device__ __align__(16) int g_dst[E_EDGES];
__device__ int      g_csr_src[E_EDGES];     // src indices sorted by dst bucket
__device__ int      g_cnt[N_NODES];         // in-degree histogram
__device__ int      g_ptr[N_NODES + 1];     // CSR row pointers
__device__ int      g_cur[N_NODES];         // scatter cursors
__device__ int      g_bsum[1024];           // per-block sums for scan
__device__ unsigned g_hi_or;                // dtype probe accumulator

__device__ __forceinline__ float leaky(float l) {
    return l > 0.0f ? l : NEG_SLOPE * l;
}

// -------- K0: zero histogram + probe flag --------
__global__ void init_kernel(int N) {
    int i = blockIdx.x * blockDim.x + threadIdx.x;
    if (i < N) g_cnt[i] = 0;
    if (i == 0) g_hi_or = 0u;
}

// -------- K0b: probe edge-index dtype (int64 vs int32) --------
__global__ void detect_kernel(const unsigned* __restrict__ ei32) {
    int i = blockIdx.x * blockDim.x + threadIdx.x;   // 1024 threads
    unsigned v = ei32[2 * i + 1];
    #pragma unroll
    for (int off = 16; off > 0; off >>= 1)
        v |= __shfl_xor_sync(0xffffffffu, v, off);
    if ((threadIdx.x & 31) == 0 && v) atomicOr(&g_hi_or, v);
}

// -------- K0c: normalize edges into int32 src/dst --------
__global__ void convert_kernel(const void* __restrict__ ei, int E) {
    int i = blockIdx.x * blockDim.x + threadIdx.x;
    if (i >= E) return;
    if (g_hi_or == 0u) {  // int64 layout
        const long long* p = (const long long*)ei;
        g_src[i] = (int)p[i];
        g_dst[i] = (int)p[(size_t)E + i];
    } else {              // int32 layout
        const int* p = (const int*)ei;
        g_src[i] = p[i];
        g_dst[i] = p[E + i];
    }
}

// -------- K1: h = x @ W, fused s_src = h.a_src, s_dst = h.a_dst --------
__global__ __launch_bounds__(256) void gemm_kernel(
    const float* __restrict__ x, const float* __restrict__ W,
    const float* __restrict__ a_src, const float* __restrict__ a_dst, int N)
{
    __shared__ float xs[128][33];
    __shared__ __align__(16) float ws[32][OUT_C];

    const int tid = threadIdx.x;
    const int t = tid & 7;
    const int group = tid >> 3;
    const int nodeBase = blockIdx.x * 128;

    float acc[4][8];
    #pragma unroll
    for (int m = 0; m < 4; m++)
        #pragma unroll
        for (int j = 0; j < 8; j++) acc[m][j] = 0.0f;

    for (int kc = 0; kc < IN_C; kc += 32) {
        __syncthreads();
        #pragma unroll
        for (int r = 0; r < 4; r++) {
            int i = tid + r * 256;
            int nl = i >> 3, f4 = i & 7;
            int gn = nodeBase + nl;
            float4 v = make_float4(0.f, 0.f, 0.f, 0.f);
            if (gn < N) v = *(const float4*)(x + (size_t)gn * IN_C + kc + f4 * 4);
            xs[nl][f4 * 4 + 0] = v.x; xs[nl][f4 * 4 + 1] = v.y;
            xs[nl][f4 * 4 + 2] = v.z; xs[nl][f4 * 4 + 3] = v.w;
        }
        #pragma unroll
        for (int r = 0; r < 2; r++) {
            int i = tid + r * 256;
            int kk = i >> 4, c = (i & 15) * 4;
            *(float4*)&ws[kk][c] = *(const float4*)(W + (size_t)(kc + kk) * OUT_C + c);
        }
        __syncthreads();
        #pragma unroll
        for (int k = 0; k < 32; k++) {
            float4 w0 = *(float4*)&ws[k][t * 8];
            float4 w1 = *(float4*)&ws[k][t * 8 + 4];
            #pragma unroll
            for (int m = 0; m < 4; m++) {
                float xv = xs[group * 4 + m][k];
                acc[m][0] += xv * w0.x; acc[m][1] += xv * w0.y;
                acc[m][2] += xv * w0.z; acc[m][3] += xv * w0.w;
                acc[m][4] += xv * w1.x; acc[m][5] += xv * w1.y;
                acc[m][6] += xv * w1.z; acc[m][7] += xv * w1.w;
            }
        }
    }

    float as[8], ad[8];
    #pragma unroll
    for (int j = 0; j < 8; j++) { as[j] = a_src[t * 8 + j]; ad[j] = a_dst[t * 8 + j]; }

    #pragma unroll
    for (int m = 0; m < 4; m++) {
        int node = nodeBase + group * 4 + m;
        float ps = 0.f, pd = 0.f;
        #pragma unroll
        for (int j = 0; j < 8; j++) { ps += acc[m][j] * as[j]; pd += acc[m][j] * ad[j]; }
        #pragma unroll
        for (int off = 4; off > 0; off >>= 1) {
            ps += __shfl_xor_sync(0xffffffffu, ps, off);
            pd += __shfl_xor_sync(0xffffffffu, pd, off);
        }
        if (node < N) {
            *(float4*)(g_h + (size_t)node * OUT_C + t * 8) =
                make_float4(acc[m][0], acc[m][1], acc[m][2], acc[m][3]);
            *(float4*)(g_h + (size_t)node * OUT_C + t * 8 + 4) =
                make_float4(acc[m][4], acc[m][5], acc[m][6], acc[m][7]);
            if (t == 0) { g_ssrc[node] = ps; g_sdst[node] = pd; }
        }
    }
}

// -------- K2: in-degree histogram --------
__global__ void hist_kernel(int E) {
    int i = blockIdx.x * blockDim.x + threadIdx.x;
    if (i < E) atomicAdd(&g_cnt[g_dst[i]], 1);
}

// -------- K3a: per-block sums of g_cnt --------
__global__ __launch_bounds__(256) void bsum_kernel(int N) {
    int i = blockIdx.x * 256 + threadIdx.x;
    int v = (i < N) ? g_cnt[i] : 0;
    #pragma unroll
    for (int off = 16; off > 0; off >>= 1)
        v += __shfl_xor_sync(0xffffffffu, v, off);
    __shared__ int sh[8];
    int lane = threadIdx.x & 31, wid = threadIdx.x >> 5;
    if (lane == 0) sh[wid] = v;
    __syncthreads();
    if (wid == 0) {
        int s = (lane < 8) ? sh[lane] : 0;
        #pragma unroll
        for (int off = 4; off > 0; off >>= 1)
            s += __shfl_xor_sync(0xffffffffu, s, off);
        if (lane == 0) g_bsum[blockIdx.x] = s;
    }
}

// -------- K3b: exclusive scan of block sums (nb <= 512, one block) --------
__global__ __launch_bounds__(512) void bscan_kernel(int nb, int N) {
    int tid = threadIdx.x, lane = tid & 31, wid = tid >> 5;
    int v = (tid < nb) ? g_bsum[tid] : 0;
    int x = v;
    #pragma unroll
    for (int off = 1; off < 32; off <<= 1) {
        int t = __shfl_up_sync(0xffffffffu, x, off);
        if (lane >= off) x += t;
    }
    __shared__ int sh[16];
    if (lane == 31) sh[wid] = x;
    __syncthreads();
    if (wid == 0) {
        int y = (lane < 16) ? sh[lane] : 0;
        #pragma unroll
        for (int off = 1; off < 16; off <<= 1) {
            int t = __shfl_up_sync(0xffffffffu, y, off);
            if (lane >= off) y += t;
        }
        if (lane < 16) sh[lane] = y;
    }
    __syncthreads();
    int excl = x - v + (wid > 0 ? sh[wid - 1] : 0);
    if (tid < nb) g_bsum[tid] = excl;
    if (tid == 0) g_ptr[N] = sh[15];   // total edge count
}

// -------- K3c: per-block rescan -> row pointers + cursors --------
__global__ __launch_bounds__(256) void rescan_kernel(int N) {
    int tid = threadIdx.x, lane = tid & 31, wid = tid >> 5;
    int i = blockIdx.x * 256 + tid;
    int v = (i < N) ? g_cnt[i] : 0;
    int x = v;
    #pragma unroll
    for (int off = 1; off < 32; off <<= 1) {
        int t = __shfl_up_sync(0xffffffffu, x, off);
        if (lane >= off) x += t;
    }
    __shared__ int sh[8];
    if (lane == 31) sh[wid] = x;
    __syncthreads();
    if (wid == 0) {
        int y = (lane < 8) ? sh[lane] : 0;
        #pragma unroll
        for (int off = 1; off < 8; off <<= 1) {
            int t = __shfl_up_sync(0xffffffffu, y, off);
            if (lane >= off) y += t;
        }
        if (lane < 8) sh[lane] = y;
    }
    __syncthreads();
    int excl = x - v + (wid > 0 ? sh[wid - 1] : 0) + g_bsum[blockIdx.x];
    if (i < N) { g_ptr[i] = excl; g_cur[i] = excl; }
}

// -------- K4: scatter edges into CSR buckets --------
__global__ void csr_kernel(int E) {
    int i = blockIdx.x * blockDim.x + threadIdx.x;
    if (i >= E) return;
    int d = g_dst[i];
    int pos = atomicAdd(&g_cur[d], 1);
    g_csr_src[pos] = g_src[i];
}

// -------- K5: per-node aggregation (one warp per dst node, no atomics) ----
// online softmax over incoming edges + self-loop, then register-accumulated
// weighted gather of h[src], bias + ELU fused.
__global__ __launch_bounds__(256) void agg_kernel(
    float* __restrict__ out, const float* __restrict__ b, int N)
{
    int d = (blockIdx.x * blockDim.x + threadIdx.x) >> 5;
    int lane = threadIdx.x & 31;
    if (d >= N) return;

    int begin = g_ptr[d], end = g_ptr[d + 1];
    float sd = g_sdst[d];
    float l_self = leaky(g_ssrc[d] + sd);

    // ---- pass 1: online (max, sum) over edges; M seeded at l_self ----
    float M = l_self, S = 0.0f;
    for (int e = begin + lane; e < end; e += 32) {
        int s = g_csr_src[e];
        float l = leaky(g_ssrc[s] + sd);
        float Mn = fmaxf(M, l);
        S = S * __expf(M - Mn) + __expf(l - Mn);
        M = Mn;
    }
    // warp merge of (M, S)
    #pragma unroll
    for (int off = 16; off > 0; off >>= 1) {
        float Mo = __shfl_xor_sync(0xffffffffu, M, off);
        float So = __shfl_xor_sync(0xffffffffu, S, off);
        float Mn = fmaxf(M, Mo);
        S = S * __expf(M - Mn) + So * __expf(Mo - Mn);
        M = Mn;
    }
    S += __expf(l_self - M);            // self-loop contribution
    float invS = 1.0f / (S + EPS);

    // ---- pass 2: weighted gather; each lane owns 2 output columns ----
    float2 acc;
    {
        float cs = __expf(l_self - M) * invS;
        float2 hv = *(const float2*)(g_h + (size_t)d * OUT_C + lane * 2);
        acc.x = cs * hv.x; acc.y = cs * hv.y;
    }
    for (int eb = begin; eb < end; eb += 32) {
        int e = eb + lane;
        float coef = 0.0f; int s = 0;
        if (e < end) {
            s = g_csr_src[e];
            float l = leaky(g_ssrc[s] + sd);
            coef = __expf(l - M) * invS;
        }
        int cnt = min(32, end - eb);
        for (int j = 0; j < cnt; ++j) {
            float c = __shfl_sync(0xffffffffu, coef, j);
            int sj  = __shfl_sync(0xffffffffu, s, j);
            float2 hv = *(const float2*)(g_h + (size_t)sj * OUT_C + lane * 2);
            acc.x += c * hv.x; acc.y += c * hv.y;
        }
    }

    // ---- bias + ELU, write out ----
    float2 bb = *(const float2*)(b + lane * 2);
    float v0 = acc.x + bb.x, v1 = acc.y + bb.y;
    v0 = v0 > 0.0f ? v0 : expm1f(v0);
    v1 = v1 > 0.0f ? v1 : expm1f(v1);
    *(float2*)(out + (size_t)d * OUT_C + lane * 2) = make_float2(v0, v1);
}

extern "C" void kernel_launch(void* const* d_in, const int* in_sizes, int n_in,
                              void* d_out, int out_size) {
    const float* x     = (const float*)d_in[0];
    const void*  ei    = d_in[1];
    const float* W     = (const float*)d_in[2];
    const float* a_src = (const float*)d_in[3];
    const float* a_dst = (const float*)d_in[4];
    const float* b     = (const float*)d_in[5];
    float*       out   = (float*)d_out;

    int N = in_sizes[0] / IN_C;      // 100000
    int E = in_sizes[1] / 2;         // 1600000
    int nb = (N + 255) / 256;        // 391 scan blocks (<= 512)

    init_kernel<<<(N + 255) / 256, 256>>>(N);
    detect_kernel<<<4, 256>>>((const unsigned*)ei);
    convert_kernel<<<(E + 255) / 256, 256>>>(ei, E);
    gemm_kernel<<<(N + 127) / 128, 256>>>(x, W, a_src, a_dst, N);
    hist_kernel<<<(E + 255) / 256, 256>>>(E);
    bsum_kernel<<<nb, 256>>>(N);
    bscan_kernel<<<1, 512>>>(nb, N);
    rescan_kernel<<<nb, 256>>>(N);
    csr_kernel<<<(E + 255) / 256, 256>>>(E);
    agg_kernel<<<(N * 32 + 255) / 256, 256>>>(out, b, N);
}

// round 16
// speedup vs baseline: 1.2277x; 1.2277x over previous
#include <cuda_runtime.h>
#include <cuda_bf16.h>
#include <cstdint>

#define N_NODES 100000
#define E_EDGES 1600000
#define IN_C 128
#define OUT_C 64
#define NEG_SLOPE 0.2f
#define EPS 1e-16f

// -------- scratch (device globals; no runtime allocation allowed) --------
__device__ __align__(16) float g_h[(size_t)N_NODES * OUT_C];  // transformed features
__device__ float    g_ssrc[N_NODES];
__device__ float    g_sdst[N_NODES];
__device__ __align__(16) int g_src[E_EDGES];
__device__ __align__(16) int g_dst[E_EDGES];
__device__ int      g_csr_src[E_EDGES];     // src indices sorted by dst bucket
__device__ int      g_cnt[N_NODES];         // in-degree histogram
__device__ int      g_ptr[N_NODES + 1];     // CSR row pointers
__device__ int      g_cur[N_NODES];         // scatter cursors
__device__ int      g_bsum[1024];           // per-block sums for scan
__device__ __align__(16) float g_Whi[IN_C * OUT_C];
__device__ __align__(16) float g_Wlo[IN_C * OUT_C];
__device__ unsigned g_hi_or;                // dtype probe accumulator

__device__ __forceinline__ float leaky(float l) {
    return l > 0.0f ? l : NEG_SLOPE * l;
}

// split fp32 into tf32-exact hi (top 10 mantissa bits) + residual lo
__device__ __forceinline__ void tf32_split(float v, unsigned& hi, unsigned& lo) {
    unsigned h = __float_as_uint(v) & 0xFFFFE000u;
    hi = h;
    lo = __float_as_uint(v - __uint_as_float(h));
}

__device__ __forceinline__ void mma_tf32(float c[4], unsigned a0, unsigned a1,
                                         unsigned a2, unsigned a3,
                                         unsigned b0, unsigned b1) {
    asm volatile(
        "mma.sync.aligned.m16n8k8.row.col.f32.tf32.tf32.f32 "
        "{%0,%1,%2,%3},{%4,%5,%6,%7},{%8,%9},{%0,%1,%2,%3};\n"
        : "+f"(c[0]), "+f"(c[1]), "+f"(c[2]), "+f"(c[3])
        : "r"(a0), "r"(a1), "r"(a2), "r"(a3), "r"(b0), "r"(b1));
}

// -------- K0: zero histogram + probe flag --------
__global__ void init_kernel(int N) {
    int i = blockIdx.x * blockDim.x + threadIdx.x;
    if (i < N) g_cnt[i] = 0;
    if (i == 0) g_hi_or = 0u;
}

// -------- K0b: probe edge-index dtype (int64 vs int32) --------
__global__ void detect_kernel(const unsigned* __restrict__ ei32) {
    int i = blockIdx.x * blockDim.x + threadIdx.x;   // 1024 threads
    unsigned v = ei32[2 * i + 1];
    #pragma unroll
    for (int off = 16; off > 0; off >>= 1)
        v |= __shfl_xor_sync(0xffffffffu, v, off);
    if ((threadIdx.x & 31) == 0 && v) atomicOr(&g_hi_or, v);
}

// -------- K0c: normalize edges into int32 src/dst + fused in-degree hist ----
__global__ void convert_kernel(const void* __restrict__ ei, int E) {
    int i = blockIdx.x * blockDim.x + threadIdx.x;
    if (i >= E) return;
    int s, d;
    if (g_hi_or == 0u) {  // int64 layout
        const long long* p = (const long long*)ei;
        s = (int)p[i];
        d = (int)p[(size_t)E + i];
    } else {              // int32 layout
        const int* p = (const int*)ei;
        s = p[i];
        d = p[E + i];
    }
    g_src[i] = s;
    g_dst[i] = d;
    atomicAdd(&g_cnt[d], 1);
}

// -------- K0d: presplit W into tf32 hi/lo --------
__global__ void wprep_kernel(const float* __restrict__ W) {
    int i = blockIdx.x * blockDim.x + threadIdx.x;
    if (i >= IN_C * OUT_C) return;
    float v = W[i];
    unsigned hi, lo;
    tf32_split(v, hi, lo);
    g_Whi[i] = __uint_as_float(hi);
    g_Wlo[i] = __uint_as_float(lo);
}

// -------- K1: h = x @ W via tf32 tensor cores (3-pass split precision) ----
// 256 threads = 8 warps, 16 node-rows per warp -> 128 nodes/block.
// fused s_src = h.a_src, s_dst = h.a_dst in the epilogue.
__global__ __launch_bounds__(256) void gemm_tc_kernel(
    const float* __restrict__ x,
    const float* __restrict__ a_src, const float* __restrict__ a_dst, int N)
{
    __shared__ __align__(16) float xs[128][20];   // pad 20: conflict-free A frags
    __shared__ __align__(16) float wh[16][72];    // pad 72: conflict-free B frags
    __shared__ __align__(16) float wl[16][72];

    const int tid  = threadIdx.x;
    const int warp = tid >> 5, lane = tid & 31;
    const int tig  = lane & 3, grp = lane >> 2;
    const int nodeBase = blockIdx.x * 128;
    const int warpRow  = warp * 16;

    float c[8][4];
    #pragma unroll
    for (int nt = 0; nt < 8; nt++)
        #pragma unroll
        for (int j = 0; j < 4; j++) c[nt][j] = 0.0f;

    for (int kc = 0; kc < IN_C; kc += 16) {
        __syncthreads();
        // x chunk: 128 rows x 16 k = 512 float4
        #pragma unroll
        for (int r = 0; r < 2; r++) {
            int idx = tid + r * 256;
            int row = idx >> 2, f4 = idx & 3;
            int gn = nodeBase + row;
            float4 v = make_float4(0.f, 0.f, 0.f, 0.f);
            if (gn < N) v = *(const float4*)(x + (size_t)gn * IN_C + kc + f4 * 4);
            *(float4*)&xs[row][f4 * 4] = v;
        }
        // W hi/lo chunk: 16 rows x 64 = 256 float4 each
        {
            int row = tid >> 4, f4 = tid & 15;
            *(float4*)&wh[row][f4 * 4] = *(const float4*)(g_Whi + (kc + row) * OUT_C + f4 * 4);
            *(float4*)&wl[row][f4 * 4] = *(const float4*)(g_Wlo + (kc + row) * OUT_C + f4 * 4);
        }
        __syncthreads();

        #pragma unroll
        for (int ks = 0; ks < 2; ks++) {
            const int k0 = ks * 8;
            unsigned ah0, ah1, ah2, ah3, al0, al1, al2, al3;
            tf32_split(xs[warpRow + grp    ][k0 + tig    ], ah0, al0);
            tf32_split(xs[warpRow + grp + 8][k0 + tig    ], ah1, al1);
            tf32_split(xs[warpRow + grp    ][k0 + tig + 4], ah2, al2);
            tf32_split(xs[warpRow + grp + 8][k0 + tig + 4], ah3, al3);
            #pragma unroll
            for (int nt = 0; nt < 8; nt++) {
                int n = nt * 8 + grp;
                unsigned bh0 = __float_as_uint(wh[k0 + tig    ][n]);
                unsigned bh1 = __float_as_uint(wh[k0 + tig + 4][n]);
                unsigned bl0 = __float_as_uint(wl[k0 + tig    ][n]);
                unsigned bl1 = __float_as_uint(wl[k0 + tig + 4][n]);
                mma_tf32(c[nt], ah0, ah1, ah2, ah3, bh0, bh1);  // hi*hi
                mma_tf32(c[nt], ah0, ah1, ah2, ah3, bl0, bl1);  // hi*lo
                mma_tf32(c[nt], al0, al1, al2, al3, bh0, bh1);  // lo*hi
            }
        }
    }

    // ---- epilogue: store h, fused attention dots ----
    int row0 = nodeBase + warpRow + grp;
    int row1 = row0 + 8;
    float ps0 = 0.f, pd0 = 0.f, ps1 = 0.f, pd1 = 0.f;
    #pragma unroll
    for (int nt = 0; nt < 8; nt++) {
        int col = nt * 8 + 2 * tig;
        float as0 = a_src[col], as1 = a_src[col + 1];
        float ad0 = a_dst[col], ad1 = a_dst[col + 1];
        ps0 += c[nt][0] * as0 + c[nt][1] * as1;
        pd0 += c[nt][0] * ad0 + c[nt][1] * ad1;
        ps1 += c[nt][2] * as0 + c[nt][3] * as1;
        pd1 += c[nt][2] * ad0 + c[nt][3] * ad1;
        if (row0 < N)
            *(float2*)(g_h + (size_t)row0 * OUT_C + col) = make_float2(c[nt][0], c[nt][1]);
        if (row1 < N)
            *(float2*)(g_h + (size_t)row1 * OUT_C + col) = make_float2(c[nt][2], c[nt][3]);
    }
    // reduce across the 4 lanes (tig) owning each row
    #pragma unroll
    for (int off = 1; off <= 2; off <<= 1) {
        ps0 += __shfl_xor_sync(0xffffffffu, ps0, off);
        pd0 += __shfl_xor_sync(0xffffffffu, pd0, off);
        ps1 += __shfl_xor_sync(0xffffffffu, ps1, off);
        pd1 += __shfl_xor_sync(0xffffffffu, pd1, off);
    }
    if (tig == 0) {
        if (row0 < N) { g_ssrc[row0] = ps0; g_sdst[row0] = pd0; }
        if (row1 < N) { g_ssrc[row1] = ps1; g_sdst[row1] = pd1; }
    }
}

// -------- K3a: per-block sums of g_cnt --------
__global__ __launch_bounds__(256) void bsum_kernel(int N) {
    int i = blockIdx.x * 256 + threadIdx.x;
    int v = (i < N) ? g_cnt[i] : 0;
    #pragma unroll
    for (int off = 16; off > 0; off >>= 1)
        v += __shfl_xor_sync(0xffffffffu, v, off);
    __shared__ int sh[8];
    int lane = threadIdx.x & 31, wid = threadIdx.x >> 5;
    if (lane == 0) sh[wid] = v;
    __syncthreads();
    if (wid == 0) {
        int s = (lane < 8) ? sh[lane] : 0;
        #pragma unroll
        for (int off = 4; off > 0; off >>= 1)
            s += __shfl_xor_sync(0xffffffffu, s, off);
        if (lane == 0) g_bsum[blockIdx.x] = s;
    }
}

// -------- K3b: exclusive scan of block sums (nb <= 512, one block) --------
__global__ __launch_bounds__(512) void bscan_kernel(int nb, int N) {
    int tid = threadIdx.x, lane = tid & 31, wid = tid >> 5;
    int v = (tid < nb) ? g_bsum[tid] : 0;
    int x = v;
    #pragma unroll
    for (int off = 1; off < 32; off <<= 1) {
        int t = __shfl_up_sync(0xffffffffu, x, off);
        if (lane >= off) x += t;
    }
    __shared__ int sh[16];
    if (lane == 31) sh[wid] = x;
    __syncthreads();
    if (wid == 0) {
        int y = (lane < 16) ? sh[lane] : 0;
        #pragma unroll
        for (int off = 1; off < 16; off <<= 1) {
            int t = __shfl_up_sync(0xffffffffu, y, off);
            if (lane >= off) y += t;
        }
        if (lane < 16) sh[lane] = y;
    }
    __syncthreads();
    int excl = x - v + (wid > 0 ? sh[wid - 1] : 0);
    if (tid < nb) g_bsum[tid] = excl;
    if (tid == 0) g_ptr[N] = sh[15];
}

// -------- K3c: per-block rescan -> row pointers + cursors --------
__global__ __launch_bounds__(256) void rescan_kernel(int N) {
    int tid = threadIdx.x, lane = tid & 31, wid = tid >> 5;
    int i = blockIdx.x * 256 + tid;
    int v = (i < N) ? g_cnt[i] : 0;
    int x = v;
    #pragma unroll
    for (int off = 1; off < 32; off <<= 1) {
        int t = __shfl_up_sync(0xffffffffu, x, off);
        if (lane >= off) x += t;
    }
    __shared__ int sh[8];
    if (lane == 31) sh[wid] = x;
    __syncthreads();
    if (wid == 0) {
        int y = (lane < 8) ? sh[lane] : 0;
        #pragma unroll
        for (int off = 1; off < 8; off <<= 1) {
            int t = __shfl_up_sync(0xffffffffu, y, off);
            if (lane >= off) y += t;
        }
        if (lane < 8) sh[lane] = y;
    }
    __syncthreads();
    int excl = x - v + (wid > 0 ? sh[wid - 1] : 0) + g_bsum[blockIdx.x];
    if (i < N) { g_ptr[i] = excl; g_cur[i] = excl; }
}

// -------- K4: scatter edges into CSR buckets --------
__global__ void csr_kernel(int E) {
    int i = blockIdx.x * blockDim.x + threadIdx.x;
    if (i >= E) return;
    int d = g_dst[i];
    int pos = atomicAdd(&g_cur[d], 1);
    g_csr_src[pos] = g_src[i];
}

// -------- K5: per-node aggregation (one warp per dst node, no atomics) ----
__global__ __launch_bounds__(256) void agg_kernel(
    float* __restrict__ out, const float* __restrict__ b, int N)
{
    int d = (blockIdx.x * blockDim.x + threadIdx.x) >> 5;
    int lane = threadIdx.x & 31;
    if (d >= N) return;

    int begin = g_ptr[d], end = g_ptr[d + 1];
    float sd = g_sdst[d];
    float l_self = leaky(g_ssrc[d] + sd);

    // ---- pass 1: online (max, sum) over edges; M seeded at l_self ----
    float M = l_self, S = 0.0f;
    for (int e = begin + lane; e < end; e += 32) {
        int s = g_csr_src[e];
        float l = leaky(g_ssrc[s] + sd);
        float Mn = fmaxf(M, l);
        S = S * __expf(M - Mn) + __expf(l - Mn);
        M = Mn;
    }
    #pragma unroll
    for (int off = 16; off > 0; off >>= 1) {
        float Mo = __shfl_xor_sync(0xffffffffu, M, off);
        float So = __shfl_xor_sync(0xffffffffu, S, off);
        float Mn = fmaxf(M, Mo);
        S = S * __expf(M - Mn) + So * __expf(Mo - Mn);
        M = Mn;
    }
    S += __expf(l_self - M);
    float invS = 1.0f / (S + EPS);

    // ---- pass 2: weighted gather; each lane owns 2 output columns ----
    float2 acc;
    {
        float cs = __expf(l_self - M) * invS;
        float2 hv = *(const float2*)(g_h + (size_t)d * OUT_C + lane * 2);
        acc.x = cs * hv.x; acc.y = cs * hv.y;
    }
    for (int eb = begin; eb < end; eb += 32) {
        int e = eb + lane;
        float coef = 0.0f; int s = 0;
        if (e < end) {
            s = g_csr_src[e];
            float l = leaky(g_ssrc[s] + sd);
            coef = __expf(l - M) * invS;
        }
        int cnt = min(32, end - eb);
        for (int j = 0; j < cnt; ++j) {
            float c = __shfl_sync(0xffffffffu, coef, j);
            int sj  = __shfl_sync(0xffffffffu, s, j);
            float2 hv = *(const float2*)(g_h + (size_t)sj * OUT_C + lane * 2);
            acc.x += c * hv.x; acc.y += c * hv.y;
        }
    }

    float2 bb = *(const float2*)(b + lane * 2);
    float v0 = acc.x + bb.x, v1 = acc.y + bb.y;
    v0 = v0 > 0.0f ? v0 : expm1f(v0);
    v1 = v1 > 0.0f ? v1 : expm1f(v1);
    *(float2*)(out + (size_t)d * OUT_C + lane * 2) = make_float2(v0, v1);
}

extern "C" void kernel_launch(void* const* d_in, const int* in_sizes, int n_in,
                              void* d_out, int out_size) {
    const float* x     = (const float*)d_in[0];
    const void*  ei    = d_in[1];
    const float* W     = (const float*)d_in[2];
    const float* a_src = (const float*)d_in[3];
    const float* a_dst = (const float*)d_in[4];
    const float* b     = (const float*)d_in[5];
    float*       out   = (float*)d_out;

    int N = in_sizes[0] / IN_C;      // 100000
    int E = in_sizes[1] / 2;         // 1600000
    int nb = (N + 255) / 256;        // 391 scan blocks (<= 512)

    init_kernel<<<(N + 255) / 256, 256>>>(N);
    detect_kernel<<<4, 256>>>((const unsigned*)ei);
    convert_kernel<<<(E + 255) / 256, 256>>>(ei, E);       // + fused histogram
    wprep_kernel<<<(IN_C * OUT_C + 255) / 256, 256>>>(W);
    gemm_tc_kernel<<<(N + 127) / 128, 256>>>(x, a_src, a_dst, N);
    bsum_kernel<<<nb, 256>>>(N);
    bscan_kernel<<<1, 512>>>(nb, N);
    rescan_kernel<<<nb, 256>>>(N);
    csr_kernel<<<(E + 255) / 256, 256>>>(E);
    agg_kernel<<<(N * 32 + 255) / 256, 256>>>(out, b, N);
}

// round 17
// speedup vs baseline: 1.3727x; 1.1181x over previous
#include <cuda_runtime.h>
#include <cuda_bf16.h>
#include <cstdint>

#define N_NODES 100000
#define E_EDGES 1600000
#define IN_C 128
#define OUT_C 64
#define NEG_SLOPE 0.2f
#define EPS 1e-16f

// -------- scratch (device globals; no runtime allocation allowed) --------
__device__ __align__(16) float g_h[(size_t)N_NODES * OUT_C];  // transformed features
__device__ float    g_ssrc[N_NODES];
__device__ float    g_sdst[N_NODES];
__device__ __align__(16) int g_src[E_EDGES];
__device__ __align__(16) int g_dst[E_EDGES];
__device__ int      g_csr_src[E_EDGES];     // src indices sorted by dst bucket
__device__ int      g_cnt[N_NODES];         // in-degree histogram
__device__ int      g_ptr[N_NODES + 1];     // CSR row pointers
__device__ int      g_cur[N_NODES];         // scatter cursors
__device__ int      g_bsum[1024];           // per-block sums for scan
__device__ unsigned g_hi_or;                // dtype probe accumulator

__device__ __forceinline__ float leaky(float l) {
    return l > 0.0f ? l : NEG_SLOPE * l;
}

// split fp32 into tf32-exact hi (top 10 mantissa bits) + residual lo
__device__ __forceinline__ void tf32_split(float v, unsigned& hi, unsigned& lo) {
    unsigned h = __float_as_uint(v) & 0xFFFFE000u;
    hi = h;
    lo = __float_as_uint(v - __uint_as_float(h));
}

__device__ __forceinline__ void mma_tf32(float c[4], unsigned a0, unsigned a1,
                                         unsigned a2, unsigned a3,
                                         unsigned b0, unsigned b1) {
    asm volatile(
        "mma.sync.aligned.m16n8k8.row.col.f32.tf32.tf32.f32 "
        "{%0,%1,%2,%3},{%4,%5,%6,%7},{%8,%9},{%0,%1,%2,%3};\n"
        : "+f"(c[0]), "+f"(c[1]), "+f"(c[2]), "+f"(c[3])
        : "r"(a0), "r"(a1), "r"(a2), "r"(a3), "r"(b0), "r"(b1));
}

// -------- K0: zero histogram + probe flag --------
__global__ void init_kernel(int N) {
    int i = blockIdx.x * blockDim.x + threadIdx.x;
    if (i < N) g_cnt[i] = 0;
    if (i == 0) g_hi_or = 0u;
}

// -------- K0b: probe edge-index dtype (int64 vs int32) --------
__global__ void detect_kernel(const unsigned* __restrict__ ei32) {
    int i = blockIdx.x * blockDim.x + threadIdx.x;   // 1024 threads
    unsigned v = ei32[2 * i + 1];
    #pragma unroll
    for (int off = 16; off > 0; off >>= 1)
        v |= __shfl_xor_sync(0xffffffffu, v, off);
    if ((threadIdx.x & 31) == 0 && v) atomicOr(&g_hi_or, v);
}

// -------- K0c: normalize edges into int32 src/dst + fused in-degree hist ----
__global__ void convert_kernel(const void* __restrict__ ei, int E) {
    int i = blockIdx.x * blockDim.x + threadIdx.x;
    if (i >= E) return;
    int s, d;
    if (g_hi_or == 0u) {  // int64 layout
        const long long* p = (const long long*)ei;
        s = (int)p[i];
        d = (int)p[(size_t)E + i];
    } else {              // int32 layout
        const int* p = (const int*)ei;
        s = p[i];
        d = p[E + i];
    }
    g_src[i] = s;
    g_dst[i] = d;
    atomicAdd(&g_cnt[d], 1);
}

// -------- K1: h = x @ W via tf32 tensor cores (3-pass split precision) ----
// W hi/lo split done inline on the SMEM tile load (no wprep pass).
__global__ __launch_bounds__(256) void gemm_tc_kernel(
    const float* __restrict__ x, const float* __restrict__ W,
    const float* __restrict__ a_src, const float* __restrict__ a_dst, int N)
{
    __shared__ __align__(16) float xs[128][20];   // pad 20: conflict-free A frags
    __shared__ __align__(16) float wh[16][72];    // pad 72: conflict-free B frags
    __shared__ __align__(16) float wl[16][72];

    const int tid  = threadIdx.x;
    const int warp = tid >> 5, lane = tid & 31;
    const int tig  = lane & 3, grp = lane >> 2;
    const int nodeBase = blockIdx.x * 128;
    const int warpRow  = warp * 16;

    float c[8][4];
    #pragma unroll
    for (int nt = 0; nt < 8; nt++)
        #pragma unroll
        for (int j = 0; j < 4; j++) c[nt][j] = 0.0f;

    for (int kc = 0; kc < IN_C; kc += 16) {
        __syncthreads();
        // x chunk: 128 rows x 16 k = 512 float4
        #pragma unroll
        for (int r = 0; r < 2; r++) {
            int idx = tid + r * 256;
            int row = idx >> 2, f4 = idx & 3;
            int gn = nodeBase + row;
            float4 v = make_float4(0.f, 0.f, 0.f, 0.f);
            if (gn < N) v = *(const float4*)(x + (size_t)gn * IN_C + kc + f4 * 4);
            *(float4*)&xs[row][f4 * 4] = v;
        }
        // W chunk: 16 rows x 64, split hi/lo inline
        {
            int row = tid >> 4, f4 = tid & 15;
            float4 v = *(const float4*)(W + (size_t)(kc + row) * OUT_C + f4 * 4);
            float4 h4, l4;
            unsigned hu, lu;
            tf32_split(v.x, hu, lu); h4.x = __uint_as_float(hu); l4.x = __uint_as_float(lu);
            tf32_split(v.y, hu, lu); h4.y = __uint_as_float(hu); l4.y = __uint_as_float(lu);
            tf32_split(v.z, hu, lu); h4.z = __uint_as_float(hu); l4.z = __uint_as_float(lu);
            tf32_split(v.w, hu, lu); h4.w = __uint_as_float(hu); l4.w = __uint_as_float(lu);
            *(float4*)&wh[row][f4 * 4] = h4;
            *(float4*)&wl[row][f4 * 4] = l4;
        }
        __syncthreads();

        #pragma unroll
        for (int ks = 0; ks < 2; ks++) {
            const int k0 = ks * 8;
            unsigned ah0, ah1, ah2, ah3, al0, al1, al2, al3;
            tf32_split(xs[warpRow + grp    ][k0 + tig    ], ah0, al0);
            tf32_split(xs[warpRow + grp + 8][k0 + tig    ], ah1, al1);
            tf32_split(xs[warpRow + grp    ][k0 + tig + 4], ah2, al2);
            tf32_split(xs[warpRow + grp + 8][k0 + tig + 4], ah3, al3);
            #pragma unroll
            for (int nt = 0; nt < 8; nt++) {
                int n = nt * 8 + grp;
                unsigned bh0 = __float_as_uint(wh[k0 + tig    ][n]);
                unsigned bh1 = __float_as_uint(wh[k0 + tig + 4][n]);
                unsigned bl0 = __float_as_uint(wl[k0 + tig    ][n]);
                unsigned bl1 = __float_as_uint(wl[k0 + tig + 4][n]);
                mma_tf32(c[nt], ah0, ah1, ah2, ah3, bh0, bh1);  // hi*hi
                mma_tf32(c[nt], ah0, ah1, ah2, ah3, bl0, bl1);  // hi*lo
                mma_tf32(c[nt], al0, al1, al2, al3, bh0, bh1);  // lo*hi
            }
        }
    }

    // ---- epilogue: store h, fused attention dots ----
    int row0 = nodeBase + warpRow + grp;
    int row1 = row0 + 8;
    float ps0 = 0.f, pd0 = 0.f, ps1 = 0.f, pd1 = 0.f;
    #pragma unroll
    for (int nt = 0; nt < 8; nt++) {
        int col = nt * 8 + 2 * tig;
        float as0 = a_src[col], as1 = a_src[col + 1];
        float ad0 = a_dst[col], ad1 = a_dst[col + 1];
        ps0 += c[nt][0] * as0 + c[nt][1] * as1;
        pd0 += c[nt][0] * ad0 + c[nt][1] * ad1;
        ps1 += c[nt][2] * as0 + c[nt][3] * as1;
        pd1 += c[nt][2] * ad0 + c[nt][3] * ad1;
        if (row0 < N)
            *(float2*)(g_h + (size_t)row0 * OUT_C + col) = make_float2(c[nt][0], c[nt][1]);
        if (row1 < N)
            *(float2*)(g_h + (size_t)row1 * OUT_C + col) = make_float2(c[nt][2], c[nt][3]);
    }
    #pragma unroll
    for (int off = 1; off <= 2; off <<= 1) {
        ps0 += __shfl_xor_sync(0xffffffffu, ps0, off);
        pd0 += __shfl_xor_sync(0xffffffffu, pd0, off);
        ps1 += __shfl_xor_sync(0xffffffffu, ps1, off);
        pd1 += __shfl_xor_sync(0xffffffffu, pd1, off);
    }
    if (tig == 0) {
        if (row0 < N) { g_ssrc[row0] = ps0; g_sdst[row0] = pd0; }
        if (row1 < N) { g_ssrc[row1] = ps1; g_sdst[row1] = pd1; }
    }
}

// -------- K3a: per-block sums of g_cnt --------
__global__ __launch_bounds__(256) void bsum_kernel(int N) {
    int i = blockIdx.x * 256 + threadIdx.x;
    int v = (i < N) ? g_cnt[i] : 0;
    #pragma unroll
    for (int off = 16; off > 0; off >>= 1)
        v += __shfl_xor_sync(0xffffffffu, v, off);
    __shared__ int sh[8];
    int lane = threadIdx.x & 31, wid = threadIdx.x >> 5;
    if (lane == 0) sh[wid] = v;
    __syncthreads();
    if (wid == 0) {
        int s = (lane < 8) ? sh[lane] : 0;
        #pragma unroll
        for (int off = 4; off > 0; off >>= 1)
            s += __shfl_xor_sync(0xffffffffu, s, off);
        if (lane == 0) g_bsum[blockIdx.x] = s;
    }
}

// -------- K3b: exclusive scan of block sums (nb <= 512, one block) --------
__global__ __launch_bounds__(512) void bscan_kernel(int nb, int N) {
    int tid = threadIdx.x, lane = tid & 31, wid = tid >> 5;
    int v = (tid < nb) ? g_bsum[tid] : 0;
    int x = v;
    #pragma unroll
    for (int off = 1; off < 32; off <<= 1) {
        int t = __shfl_up_sync(0xffffffffu, x, off);
        if (lane >= off) x += t;
    }
    __shared__ int sh[16];
    if (lane == 31) sh[wid] = x;
    __syncthreads();
    if (wid == 0) {
        int y = (lane < 16) ? sh[lane] : 0;
        #pragma unroll
        for (int off = 1; off < 16; off <<= 1) {
            int t = __shfl_up_sync(0xffffffffu, y, off);
            if (lane >= off) y += t;
        }
        if (lane < 16) sh[lane] = y;
    }
    __syncthreads();
    int excl = x - v + (wid > 0 ? sh[wid - 1] : 0);
    if (tid < nb) g_bsum[tid] = excl;
    if (tid == 0) g_ptr[N] = sh[15];
}

// -------- K3c: per-block rescan -> row pointers + cursors --------
__global__ __launch_bounds__(256) void rescan_kernel(int N) {
    int tid = threadIdx.x, lane = tid & 31, wid = tid >> 5;
    int i = blockIdx.x * 256 + tid;
    int v = (i < N) ? g_cnt[i] : 0;
    int x = v;
    #pragma unroll
    for (int off = 1; off < 32; off <<= 1) {
        int t = __shfl_up_sync(0xffffffffu, x, off);
        if (lane >= off) x += t;
    }
    __shared__ int sh[8];
    if (lane == 31) sh[wid] = x;
    __syncthreads();
    if (wid == 0) {
        int y = (lane < 8) ? sh[lane] : 0;
        #pragma unroll
        for (int off = 1; off < 8; off <<= 1) {
            int t = __shfl_up_sync(0xffffffffu, y, off);
            if (lane >= off) y += t;
        }
        if (lane < 8) sh[lane] = y;
    }
    __syncthreads();
    int excl = x - v + (wid > 0 ? sh[wid - 1] : 0) + g_bsum[blockIdx.x];
    if (i < N) { g_ptr[i] = excl; g_cur[i] = excl; }
}

// -------- K4: scatter edges into CSR buckets --------
__global__ void csr_kernel(int E) {
    int i = blockIdx.x * blockDim.x + threadIdx.x;
    if (i >= E) return;
    int d = g_dst[i];
    int pos = atomicAdd(&g_cur[d], 1);
    g_csr_src[pos] = g_src[i];
}

// -------- K5: per-node aggregation (one warp per dst node, no atomics) ----
__global__ __launch_bounds__(256) void agg_kernel(
    float* __restrict__ out, const float* __restrict__ b, int N)
{
    int d = (blockIdx.x * blockDim.x + threadIdx.x) >> 5;
    int lane = threadIdx.x & 31;
    if (d >= N) return;

    int begin = g_ptr[d], end = g_ptr[d + 1];
    float sd = g_sdst[d];
    float l_self = leaky(g_ssrc[d] + sd);

    // ---- pass 1: online (max, sum) over edges; M seeded at l_self ----
    float M = l_self, S = 0.0f;
    for (int e = begin + lane; e < end; e += 32) {
        int s = g_csr_src[e];
        float l = leaky(g_ssrc[s] + sd);
        float Mn = fmaxf(M, l);
        S = S * __expf(M - Mn) + __expf(l - Mn);
        M = Mn;
    }
    #pragma unroll
    for (int off = 16; off > 0; off >>= 1) {
        float Mo = __shfl_xor_sync(0xffffffffu, M, off);
        float So = __shfl_xor_sync(0xffffffffu, S, off);
        float Mn = fmaxf(M, Mo);
        S = S * __expf(M - Mn) + So * __expf(Mo - Mn);
        M = Mn;
    }
    S += __expf(l_self - M);
    float invS = 1.0f / (S + EPS);

    // ---- pass 2: weighted gather; each lane owns 2 output columns ----
    float2 acc;
    {
        float cs = __expf(l_self - M) * invS;
        float2 hv = *(const float2*)(g_h + (size_t)d * OUT_C + lane * 2);
        acc.x = cs * hv.x; acc.y = cs * hv.y;
    }
    for (int eb = begin; eb < end; eb += 32) {
        int e = eb + lane;
        float coef = 0.0f; int s = 0;
        if (e < end) {
            s = g_csr_src[e];
            float l = leaky(g_ssrc[s] + sd);
            coef = __expf(l - M) * invS;
        }
        int cnt = min(32, end - eb);
        for (int j = 0; j < cnt; ++j) {
            float c = __shfl_sync(0xffffffffu, coef, j);
            int sj  = __shfl_sync(0xffffffffu, s, j);
            float2 hv = *(const float2*)(g_h + (size_t)sj * OUT_C + lane * 2);
            acc.x += c * hv.x; acc.y += c * hv.y;
        }
    }

    float2 bb = *(const float2*)(b + lane * 2);
    float v0 = acc.x + bb.x, v1 = acc.y + bb.y;
    v0 = v0 > 0.0f ? v0 : expm1f(v0);
    v1 = v1 > 0.0f ? v1 : expm1f(v1);
    *(float2*)(out + (size_t)d * OUT_C + lane * 2) = make_float2(v0, v1);
}

extern "C" void kernel_launch(void* const* d_in, const int* in_sizes, int n_in,
                              void* d_out, int out_size) {
    const float* x     = (const float*)d_in[0];
    const void*  ei    = d_in[1];
    const float* W     = (const float*)d_in[2];
    const float* a_src = (const float*)d_in[3];
    const float* a_dst = (const float*)d_in[4];
    const float* b     = (const float*)d_in[5];
    float*       out   = (float*)d_out;

    int N = in_sizes[0] / IN_C;      // 100000
    int E = in_sizes[1] / 2;         // 1600000
    int nb = (N + 255) / 256;        // 391 scan blocks (<= 512)

    // lazily-created side stream + fork/join events (created on the first,
    // non-captured correctness call; reused inside graph capture thereafter)
    static cudaStream_t s2 = nullptr;
    static cudaEvent_t evFork = nullptr, evJoin = nullptr;
    if (!s2) {
        cudaStreamCreateWithFlags(&s2, cudaStreamNonBlocking);
        cudaEventCreateWithFlags(&evFork, cudaEventDisableTiming);
        cudaEventCreateWithFlags(&evJoin, cudaEventDisableTiming);
    }

    // fork: GEMM chain on s2, edge/CSR chain on the default stream
    cudaEventRecord(evFork, 0);
    cudaStreamWaitEvent(s2, evFork, 0);

    gemm_tc_kernel<<<(N + 127) / 128, 256, 0, s2>>>(x, W, a_src, a_dst, N);
    cudaEventRecord(evJoin, s2);

    init_kernel<<<(N + 255) / 256, 256>>>(N);
    detect_kernel<<<4, 256>>>((const unsigned*)ei);
    convert_kernel<<<(E + 255) / 256, 256>>>(ei, E);       // + fused histogram
    bsum_kernel<<<nb, 256>>>(N);
    bscan_kernel<<<1, 512>>>(nb, N);
    rescan_kernel<<<nb, 256>>>(N);
    csr_kernel<<<(E + 255) / 256, 256>>>(E);

    // join: aggregation needs both chains
    cudaStreamWaitEvent(0, evJoin, 0);
    agg_kernel<<<(N * 32 + 255) / 256, 256>>>(out, b, N);
}